// round 2
// baseline (speedup 1.0000x reference)
#include <cuda_runtime.h>

// ScaledDotProductAttention: B=4, H=1, S=4096, D=16, fp32.
// out = [context (B*S*D) | attn (B*S*S)]
// scores = QK^T/sqrt(D) + (w*link + b); masked(true) -> -1e9; softmax; context = attn @ V.
// attn_mask arrives as int32 (harness converts bool -> int32).

#define BATCH 4
#define SEQ   4096
#define DIM   16
#define TQ    8            // queries per CTA
#define NT    256          // threads per CTA
#define NWARP (NT / 32)
#define RED_STRIDE 129     // padded stride for conflict-free context reduction

// dynamic smem: max(scores TQ*SEQ, reduction NT*RED_STRIDE) floats
#define SMEM_FLOATS (NT * RED_STRIDE)   // 33024 > TQ*SEQ = 32768
#define SMEM_BYTES  (SMEM_FLOATS * 4)   // 132096 B

__global__ __launch_bounds__(NT, 1)
void sdpa_fused_kernel(const float* __restrict__ Qp,
                       const float* __restrict__ Kp,
                       const float* __restrict__ Vp,
                       const int*   __restrict__ Mp,           // bool mask as int32
                       const float* __restrict__ Lp,           // link_sim [B,S,S]
                       const float* __restrict__ swp,          // scalar
                       const float* __restrict__ sbp,          // scalar
                       float* __restrict__ ctx,                // [B,S,D]
                       float* __restrict__ attn)               // [B,S,S]
{
    extern __shared__ float scr[];                // scores / reduction scratch
    __shared__ float qtile[TQ * DIM];
    __shared__ float red[TQ * NWARP];
    __shared__ float mfin[TQ];
    __shared__ float sfin[TQ];

    const int tid = threadIdx.x;
    const int b   = blockIdx.x / (SEQ / TQ);
    const int q0  = (blockIdx.x % (SEQ / TQ)) * TQ;

    const float w  = *swp;
    const float bb = *sbp;

    // ---- load Q tile (contiguous TQ*DIM floats) ----
    if (tid < TQ * DIM)
        qtile[tid] = Qp[((size_t)b * SEQ + q0) * DIM + tid];
    __syncthreads();

    float qreg[TQ * DIM];
    #pragma unroll
    for (int i = 0; i < TQ * DIM; i++) qreg[i] = qtile[i];

    const float4* K4 = (const float4*)(Kp + (size_t)b * SEQ * DIM);
    const float4* V4 = (const float4*)(Vp + (size_t)b * SEQ * DIM);
    const float*  Lb = Lp + (size_t)b * SEQ * SEQ;
    const int*    Mb = Mp + (size_t)b * SEQ * SEQ;
    float* Ab = attn + (size_t)b * SEQ * SEQ;

    // ================= Phase A: scores + running max =================
    float mloc[TQ];
    #pragma unroll
    for (int q = 0; q < TQ; q++) mloc[q] = -3.4e38f;

    #pragma unroll 2
    for (int k = tid; k < SEQ; k += NT) {
        float4 k0 = K4[4 * k + 0];
        float4 k1 = K4[4 * k + 1];
        float4 k2 = K4[4 * k + 2];
        float4 k3 = K4[4 * k + 3];
        float lk[TQ];
        int   mk[TQ];
        #pragma unroll
        for (int q = 0; q < TQ; q++) lk[q] = Lb[(size_t)(q0 + q) * SEQ + k];
        #pragma unroll
        for (int q = 0; q < TQ; q++) mk[q] = Mb[(size_t)(q0 + q) * SEQ + k];

        #pragma unroll
        for (int q = 0; q < TQ; q++) {
            const float* qq = &qreg[q * DIM];
            float dot;
            dot  = qq[0]  * k0.x; dot = fmaf(qq[1],  k0.y, dot);
            dot  = fmaf(qq[2],  k0.z, dot); dot = fmaf(qq[3],  k0.w, dot);
            dot  = fmaf(qq[4],  k1.x, dot); dot = fmaf(qq[5],  k1.y, dot);
            dot  = fmaf(qq[6],  k1.z, dot); dot = fmaf(qq[7],  k1.w, dot);
            dot  = fmaf(qq[8],  k2.x, dot); dot = fmaf(qq[9],  k2.y, dot);
            dot  = fmaf(qq[10], k2.z, dot); dot = fmaf(qq[11], k2.w, dot);
            dot  = fmaf(qq[12], k3.x, dot); dot = fmaf(qq[13], k3.y, dot);
            dot  = fmaf(qq[14], k3.z, dot); dot = fmaf(qq[15], k3.w, dot);
            float sc = fmaf(w, lk[q], bb);
            sc = fmaf(dot, 0.25f, sc);          // 1/sqrt(16) = 0.25
            sc = mk[q] ? -1e9f : sc;
            scr[q * SEQ + k] = sc;
            mloc[q] = fmaxf(mloc[q], sc);
        }
    }

    // ---- reduce max per q ----
    const int wp = tid >> 5, ln = tid & 31;
    #pragma unroll
    for (int q = 0; q < TQ; q++) {
        #pragma unroll
        for (int o = 16; o > 0; o >>= 1)
            mloc[q] = fmaxf(mloc[q], __shfl_xor_sync(0xffffffffu, mloc[q], o));
    }
    if (ln == 0) {
        #pragma unroll
        for (int q = 0; q < TQ; q++) red[q * NWARP + wp] = mloc[q];
    }
    __syncthreads();
    if (tid < TQ) {
        float m = red[tid * NWARP];
        #pragma unroll
        for (int t = 1; t < NWARP; t++) m = fmaxf(m, red[tid * NWARP + t]);
        mfin[tid] = m;
    }
    __syncthreads();

    // ================= Phase C: exp in place + sums =================
    float mq[TQ];
    #pragma unroll
    for (int q = 0; q < TQ; q++) mq[q] = mfin[q];
    float sloc[TQ];
    #pragma unroll
    for (int q = 0; q < TQ; q++) sloc[q] = 0.0f;

    #pragma unroll 2
    for (int k = tid; k < SEQ; k += NT) {
        #pragma unroll
        for (int q = 0; q < TQ; q++) {
            float e = __expf(scr[q * SEQ + k] - mq[q]);
            scr[q * SEQ + k] = e;
            sloc[q] += e;
        }
    }
    #pragma unroll
    for (int q = 0; q < TQ; q++) {
        #pragma unroll
        for (int o = 16; o > 0; o >>= 1)
            sloc[q] += __shfl_xor_sync(0xffffffffu, sloc[q], o);
    }
    if (ln == 0) {
        #pragma unroll
        for (int q = 0; q < TQ; q++) red[q * NWARP + wp] = sloc[q];
    }
    __syncthreads();
    if (tid < TQ) {
        float s = 0.0f;
        #pragma unroll
        for (int t = 0; t < NWARP; t++) s += red[tid * NWARP + t];
        sfin[tid] = s;
    }
    __syncthreads();

    // ================= Phase E: write attn + accumulate context =================
    float inv[TQ];
    #pragma unroll
    for (int q = 0; q < TQ; q++) inv[q] = 1.0f / sfin[q];

    float acc[TQ * DIM];
    #pragma unroll
    for (int i = 0; i < TQ * DIM; i++) acc[i] = 0.0f;

    #pragma unroll 2
    for (int k = tid; k < SEQ; k += NT) {
        float4 v0 = V4[4 * k + 0];
        float4 v1 = V4[4 * k + 1];
        float4 v2 = V4[4 * k + 2];
        float4 v3 = V4[4 * k + 3];
        #pragma unroll
        for (int q = 0; q < TQ; q++) {
            float a = scr[q * SEQ + k] * inv[q];
            Ab[(size_t)(q0 + q) * SEQ + k] = a;
            float* A = &acc[q * DIM];
            A[0]  = fmaf(a, v0.x, A[0]);  A[1]  = fmaf(a, v0.y, A[1]);
            A[2]  = fmaf(a, v0.z, A[2]);  A[3]  = fmaf(a, v0.w, A[3]);
            A[4]  = fmaf(a, v1.x, A[4]);  A[5]  = fmaf(a, v1.y, A[5]);
            A[6]  = fmaf(a, v1.z, A[6]);  A[7]  = fmaf(a, v1.w, A[7]);
            A[8]  = fmaf(a, v2.x, A[8]);  A[9]  = fmaf(a, v2.y, A[9]);
            A[10] = fmaf(a, v2.z, A[10]); A[11] = fmaf(a, v2.w, A[11]);
            A[12] = fmaf(a, v3.x, A[12]); A[13] = fmaf(a, v3.y, A[13]);
            A[14] = fmaf(a, v3.z, A[14]); A[15] = fmaf(a, v3.w, A[15]);
        }
    }
    __syncthreads();   // everyone done reading scr

    // ---- context cross-thread reduction (conflict-free padded layout) ----
    #pragma unroll
    for (int i = 0; i < TQ * DIM; i++)
        scr[(size_t)tid * RED_STRIDE + i] = acc[i];
    __syncthreads();

    if (tid < TQ * DIM) {
        float s = 0.0f;
        for (int t = 0; t < NT; t++)
            s += scr[(size_t)t * RED_STRIDE + tid];
        const int q = tid / DIM, d = tid % DIM;
        ctx[((size_t)b * SEQ + q0 + q) * DIM + d] = s;
    }
}

extern "C" void kernel_launch(void* const* d_in, const int* in_sizes, int n_in,
                              void* d_out, int out_size)
{
    const float* Q  = (const float*)d_in[0];
    const float* K  = (const float*)d_in[1];
    const float* V  = (const float*)d_in[2];
    const int*   M  = (const int*)d_in[3];
    const float* L  = (const float*)d_in[4];
    const float* sw = (const float*)d_in[5];
    const float* sb = (const float*)d_in[6];

    float* ctx  = (float*)d_out;                                   // B*S*D
    float* attn = (float*)d_out + (size_t)BATCH * SEQ * DIM;       // B*S*S

    cudaFuncSetAttribute(sdpa_fused_kernel,
                         cudaFuncAttributeMaxDynamicSharedMemorySize, SMEM_BYTES);

    dim3 grid(BATCH * (SEQ / TQ));
    sdpa_fused_kernel<<<grid, NT, SMEM_BYTES>>>(Q, K, V, M, L, sw, sb, ctx, attn);
}